// round 5
// baseline (speedup 1.0000x reference)
#include <cuda_runtime.h>
#include <cstdint>

// GRU: B=128, T=4096, I=6, H=32, O=2. One CTA per sequence, 5 warps:
//   warp 0: r,z dots + activations + h update (critical path)
//   warp 1: n-dot helper, synced via lock-free tagged smem slots (no bar.sync)
//   warp 2: FC output, one chunk behind
//   warps 3,4: gx producers, one chunk ahead
// Cross-warp protocol (all protocol traffic is st./ld.volatile => PTX program
// order holds between them):
//   warp0: st.volatile h row (contiguous 128B), then st.volatile tag word.
//   warp1: spins on tag, ld.volatile h row, computes ns, publishes {tag|ns}
//          as ONE aligned 8B volatile store per lane (atomic, no tearing).
//   warp0 polls its lane's slot for the exact step tag. Slots are initialized
//   to tag=0xFFFFFFFF (never a valid step) before the pipeline starts.

#define Bq 128
#define Tq 4096
#define Iq 6
#define Hq 32
#define Oq 2
#define CH 32
#define NCH (Tq / CH)
#define HPAD 36   // 144B rows, 16B aligned

#define KRf (-1.4426950408889634f)   // -log2(e): sigmoid(v)=rcp(1+ex2(KR*v))
#define KNf ( 2.8853900817779268f)   // 2*log2(e): tanh(v)=1-2*rcp(1+ex2(KN*v))

typedef unsigned long long u64;

__device__ __forceinline__ float ex2a(float x) { float y; asm("ex2.approx.f32 %0, %1;" : "=f"(y) : "f"(x)); return y; }
__device__ __forceinline__ float rcpa(float x) { float y; asm("rcp.approx.f32 %0, %1;" : "=f"(y) : "f"(x)); return y; }

__device__ __forceinline__ u64 pk2(float lo, float hi) { u64 r; asm("mov.b64 %0, {%1, %2};" : "=l"(r) : "f"(lo), "f"(hi)); return r; }
__device__ __forceinline__ void upk2(u64 v, float& lo, float& hi) { asm("mov.b64 {%0, %1}, %2;" : "=f"(lo), "=f"(hi) : "l"(v)); }
__device__ __forceinline__ u64 f2fma(u64 a, u64 b, u64 c) { u64 d; asm("fma.rn.f32x2 %0, %1, %2, %3;" : "=l"(d) : "l"(a), "l"(b), "l"(c)); return d; }
__device__ __forceinline__ u64 f2add(u64 a, u64 b) { u64 d; asm("add.rn.f32x2 %0, %1, %2;" : "=l"(d) : "l"(a), "l"(b)); return d; }
__device__ __forceinline__ uint32_t saddr(const void* p) {
    uint32_t a;
    asm("{ .reg .u64 t; cvta.to.shared.u64 t, %1; cvt.u32.u64 %0, t; }" : "=r"(a) : "l"(p));
    return a;
}
// volatile shared ops: PTX guarantees program order among volatile accesses
__device__ __forceinline__ void ldsv128(uint32_t a, u64& v0, u64& v1) {
    asm volatile("ld.volatile.shared.v2.b64 {%0, %1}, [%2];" : "=l"(v0), "=l"(v1) : "r"(a));
}
__device__ __forceinline__ void stvolf32(uint32_t a, float v) { asm volatile("st.volatile.shared.f32 [%0], %1;" :: "r"(a), "f"(v)); }
__device__ __forceinline__ u64 ldvol64(uint32_t a) { u64 v; asm volatile("ld.volatile.shared.b64 %0, [%1];" : "=l"(v) : "r"(a)); return v; }
__device__ __forceinline__ void stvol64(uint32_t a, u64 v) { asm volatile("st.volatile.shared.b64 [%0], %1;" :: "r"(a), "l"(v)); }
__device__ __forceinline__ uint32_t ldvol32(uint32_t a) { uint32_t v; asm volatile("ld.volatile.shared.b32 %0, [%1];" : "=r"(v) : "r"(a)); return v; }
__device__ __forceinline__ void stvol32(uint32_t a, uint32_t v) { asm volatile("st.volatile.shared.b32 [%0], %1;" :: "r"(a), "r"(v)); }

__device__ __forceinline__ float hsum4(u64 a0, u64 a1, u64 a2, u64 a3) {
    u64 s = f2add(f2add(a0, a1), f2add(a2, a3));
    float lo, hi; upk2(s, lo, hi);
    return lo + hi;
}

__global__ void __launch_bounds__(160, 1) gru_seq_kernel(
    const float* __restrict__ x,        // [B, T, I]
    const int*   __restrict__ lengths,  // [B]
    const float* __restrict__ w_ih,     // [3H, I]
    const float* __restrict__ w_hh,     // [3H, H]
    const float* __restrict__ b_ih,     // [3H]
    const float* __restrict__ b_hh,     // [3H]
    const float* __restrict__ fc_w,     // [O, H]
    const float* __restrict__ fc_b,     // [O]
    float* __restrict__ out)            // [B, T, O]
{
    __shared__ __align__(16) float4 s_gx[2][CH][Hq];  // {pr, pz, pn, 0}
    __shared__ __align__(16) float s_h[2][CH][HPAD];  // h ring
    __shared__ __align__(16) u64 s_ns[Hq];            // {tag<<32 | ns_bits} per lane
    __shared__ unsigned s_tag;                        // # of completed h rows

    const int lane = threadIdx.x & 31;
    const int warp = threadIdx.x >> 5;
    const int b = blockIdx.x;
    const int L = lengths[b];

    const uint32_t hbase  = saddr(&s_h[0][0][0]);
    const uint32_t nsaddr = saddr(&s_ns[0]) + lane * 8;
    const uint32_t tagaddr = saddr(&s_tag);

    if (warp == 0) {
        // ================= r,z dots + assembly =================
        u64 wr[16], wz[16];
        const float* rr = w_hh + lane * Hq;
        const float* rz = w_hh + (Hq + lane) * Hq;
#pragma unroll
        for (int j = 0; j < 16; j++) {
            wr[j] = pk2(KRf * rr[2 * j], KRf * rr[2 * j + 1]);
            wz[j] = pk2(KRf * rz[2 * j], KRf * rz[2 * j + 1]);
        }
        s_h[1][CH - 1][lane] = 0.0f;   // initial h_{-1} = 0 row
        if (lane == 0) s_tag = 0u;     // visible after chunk-0 __syncthreads
        float hk = 0.f;
        uint32_t hprev = hbase + ((1 * CH + (CH - 1)) * HPAD) * 4;
        unsigned g = 0;   // global step counter

        for (int c = 0; c < NCH; c++) {
            __syncthreads();
            int nst = L - c * CH;
            nst = nst < 0 ? 0 : (nst > CH ? CH : nst);
            uint32_t hrow = hbase + ((c & 1) * CH * HPAD) * 4;
            float4 gx = s_gx[c & 1][0][lane];
#pragma unroll 1
            for (int s = 0; s < nst; s++) {
                __syncwarp();   // order own h stores (prev step) vs these loads
                const ulonglong2* hp2 = reinterpret_cast<const ulonglong2*>(
                    reinterpret_cast<const char*>(s_h) + (hprev - hbase));
                u64 hp[16];
#pragma unroll
                for (int j = 0; j < 8; j++) { ulonglong2 t = hp2[j]; hp[2 * j] = t.x; hp[2 * j + 1] = t.y; }

                u64 ar0 = pk2(gx.x, 0.f), ar1 = 0ull, ar2 = 0ull, ar3 = 0ull;
#pragma unroll
                for (int j = 0; j < 16; j += 4) {   // r first: critical path
                    ar0 = f2fma(wr[j], hp[j], ar0);
                    ar1 = f2fma(wr[j + 1], hp[j + 1], ar1);
                    ar2 = f2fma(wr[j + 2], hp[j + 2], ar2);
                    ar3 = f2fma(wr[j + 3], hp[j + 3], ar3);
                }
                float rs = hsum4(ar0, ar1, ar2, ar3);
                float er = ex2a(rs);                 // MUFU stall: z-FMAs fill it
                u64 az0 = pk2(gx.y, 0.f), az1 = 0ull, az2 = 0ull, az3 = 0ull;
#pragma unroll
                for (int j = 0; j < 16; j += 4) {
                    az0 = f2fma(wz[j], hp[j], az0);
                    az1 = f2fma(wz[j + 1], hp[j + 1], az1);
                    az2 = f2fma(wz[j + 2], hp[j + 2], az2);
                    az3 = f2fma(wz[j + 3], hp[j + 3], az3);
                }
                float zs = hsum4(az0, az1, az2, az3);
                float ez = ex2a(zs);
                float pn = gx.z;
                if (s + 1 < nst) gx = s_gx[c & 1][s + 1][lane];   // prefetch next gx
                float r = rcpa(1.0f + er);
                float z = rcpa(1.0f + ez);

                // poll warp1's {tag|ns} slot (usually ready on first read)
                u64 v = ldvol64(nsaddr);
                while (__any_sync(0xffffffffu, (unsigned)(v >> 32) != g))
                    v = ldvol64(nsaddr);
                float ns = __uint_as_float((unsigned)v);

                float q = rcpa(1.0f + ex2a(fmaf(r, ns, pn)));
                float omz = 1.0f - z;
                float c0 = fmaf(z, hk, omz);
                float c1 = -2.0f * omz;
                hk = fmaf(c1, q, c0);                // h_new

                stvolf32(hrow + lane * 4, hk);       // volatile: ordered before tag
                g++;
                stvol32(tagaddr, g);                 // volatile: after h in prog order
                hprev = hrow;
                hrow += HPAD * 4;
            }
        }
        __syncthreads();
    } else if (warp == 1) {
        // ================= n-dot helper =================
        u64 wn[16];
        const float* rn = w_hh + (2 * Hq + lane) * Hq;
#pragma unroll
        for (int j = 0; j < 16; j++)
            wn[j] = pk2(KNf * rn[2 * j], KNf * rn[2 * j + 1]);
        const u64 bhn_pk = pk2(KNf * b_hh[2 * Hq + lane], 0.0f);
        uint32_t hprev = hbase + ((1 * CH + (CH - 1)) * HPAD) * 4;
        unsigned g = 0;
        // CRITICAL: invalidate my slot before the pipeline starts (tag that can
        // never equal a valid step id). Without this, stale/zero smem can
        // satisfy warp0's very first poll with garbage ns.
        stvol64(nsaddr, 0xFFFFFFFF00000000ull);

        for (int c = 0; c < NCH; c++) {
            __syncthreads();
            int nst = L - c * CH;
            nst = nst < 0 ? 0 : (nst > CH ? CH : nst);
            uint32_t hrow = hbase + ((c & 1) * CH * HPAD) * 4;
#pragma unroll 1
            for (int s = 0; s < nst; s++) {
                while (ldvol32(tagaddr) != g) { }    // wait for h_{g-1}
                u64 hp[16];
#pragma unroll
                for (int j = 0; j < 8; j++) ldsv128(hprev + 16 * j, hp[2 * j], hp[2 * j + 1]);
                u64 an0 = bhn_pk, an1 = 0ull, an2 = 0ull, an3 = 0ull;
#pragma unroll
                for (int j = 0; j < 16; j += 4) {
                    an0 = f2fma(wn[j], hp[j], an0);
                    an1 = f2fma(wn[j + 1], hp[j + 1], an1);
                    an2 = f2fma(wn[j + 2], hp[j + 2], an2);
                    an3 = f2fma(wn[j + 3], hp[j + 3], an3);
                }
                float ns = hsum4(an0, an1, an2, an3);
                stvol64(nsaddr, ((u64)g << 32) | (u64)__float_as_uint(ns));
                g++;
                hprev = hrow;
                hrow += HPAD * 4;
            }
        }
        __syncthreads();
    } else if (warp == 2) {
        // ================= FC output, one chunk behind =================
        for (int c = 0; c < NCH; c++) {
            __syncthreads();
            if (c > 0) {
                const int cp = c - 1;
                const int t = cp * CH + lane;
                float o0 = __ldg(fc_b + 0);
                float o1 = __ldg(fc_b + 1);
                if (t < L) {
                    const float* hr = &s_h[cp & 1][lane][0];
#pragma unroll
                    for (int j = 0; j < Hq; j++) {
                        float hv = hr[j];
                        o0 = fmaf(__ldg(fc_w + j), hv, o0);
                        o1 = fmaf(__ldg(fc_w + Hq + j), hv, o1);
                    }
                }
                float2 v = make_float2(o0, o1);
                *reinterpret_cast<float2*>(out + ((size_t)b * Tq + t) * Oq) = v;
            }
        }
        __syncthreads();
        {   // epilogue: last chunk
            const int cp = NCH - 1;
            const int t = cp * CH + lane;
            float o0 = __ldg(fc_b + 0);
            float o1 = __ldg(fc_b + 1);
            if (t < L) {
                const float* hr = &s_h[cp & 1][lane][0];
#pragma unroll
                for (int j = 0; j < Hq; j++) {
                    float hv = hr[j];
                    o0 = fmaf(__ldg(fc_w + j), hv, o0);
                    o1 = fmaf(__ldg(fc_w + Hq + j), hv, o1);
                }
            }
            float2 v = make_float2(o0, o1);
            *reinterpret_cast<float2*>(out + ((size_t)b * Tq + t) * Oq) = v;
        }
    } else {
        // ================= producers (warps 3,4), one chunk ahead =================
        float wiA[Iq], wiB[Iq], wiC[Iq];
#pragma unroll
        for (int i = 0; i < Iq; i++) {
            wiA[i] = w_ih[lane * Iq + i];
            wiB[i] = w_ih[(Hq + lane) * Iq + i];
            wiC[i] = w_ih[(2 * Hq + lane) * Iq + i];
        }
        const float biA = b_ih[lane] + b_hh[lane];
        const float biB = b_ih[Hq + lane] + b_hh[Hq + lane];
        const float biC = b_ih[2 * Hq + lane];
        const int s0 = (warp == 4) ? (CH / 2) : 0;

        // prologue: chunk 0
        {
            const float* xp = x + ((size_t)b * Tq + s0) * Iq;
#pragma unroll 1
            for (int s = 0; s < CH / 2; s++) {
                float xv[Iq];
#pragma unroll
                for (int i = 0; i < Iq; i++) xv[i] = xp[i];
                float gr = biA, gz = biB, gn = biC;
#pragma unroll
                for (int i = 0; i < Iq; i++) {
                    gr = fmaf(wiA[i], xv[i], gr);
                    gz = fmaf(wiB[i], xv[i], gz);
                    gn = fmaf(wiC[i], xv[i], gn);
                }
                s_gx[0][s0 + s][lane] = make_float4(KRf * gr, KRf * gz, KNf * gn, 0.0f);
                xp += Iq;
            }
        }
        for (int c = 0; c < NCH; c++) {
            __syncthreads();
            const int cc = c + 1;
            if (cc < NCH) {
                const float* xp = x + ((size_t)b * Tq + cc * CH + s0) * Iq;
#pragma unroll 1
                for (int s = 0; s < CH / 2; s++) {
                    float xv[Iq];
#pragma unroll
                    for (int i = 0; i < Iq; i++) xv[i] = xp[i];
                    float gr = biA, gz = biB, gn = biC;
#pragma unroll
                    for (int i = 0; i < Iq; i++) {
                        gr = fmaf(wiA[i], xv[i], gr);
                        gz = fmaf(wiB[i], xv[i], gz);
                        gn = fmaf(wiC[i], xv[i], gn);
                    }
                    s_gx[cc & 1][s0 + s][lane] = make_float4(KRf * gr, KRf * gz, KNf * gn, 0.0f);
                    xp += Iq;
                }
            }
        }
        __syncthreads();
    }
}

extern "C" void kernel_launch(void* const* d_in, const int* in_sizes, int n_in,
                              void* d_out, int out_size) {
    const float* x       = (const float*)d_in[0];
    const int*   lengths = (const int*)d_in[1];
    const float* w_ih    = (const float*)d_in[2];
    const float* w_hh    = (const float*)d_in[3];
    const float* b_ih    = (const float*)d_in[4];
    const float* b_hh    = (const float*)d_in[5];
    const float* fc_w    = (const float*)d_in[6];
    const float* fc_b    = (const float*)d_in[7];
    float* out = (float*)d_out;

    gru_seq_kernel<<<Bq, 160>>>(x, lengths, w_ih, w_hh, b_ih, b_hh, fc_w, fc_b, out);
}

// round 6
// speedup vs baseline: 1.8071x; 1.8071x over previous
#include <cuda_runtime.h>
#include <cstdint>

// GRU: B=128, T=4096, I=6, H=32, O=2. One CTA per sequence, 4 warps:
//   warp 0: full recurrence (critical path), exclusive SMSP0
//   warp 1: FC output, one chunk behind
//   warps 2,3: gx producers, one chunk ahead
// Single-warp recurrence; activations via MUFU tanh.approx:
//   sigmoid(v) = 0.5 + 0.5*tanh(v/2)  (the /2 folded into weights/producers)
//   h broadcast: volatile STS then volatile LDS (same converged warp, smem
//   wavefronts in order -> no __syncwarp needed on the critical path).

#define Bq 128
#define Tq 4096
#define Iq 6
#define Hq 32
#define Oq 2
#define CH 32
#define NCH (Tq / CH)
#define HPAD 36   // 144B rows, 16B aligned

typedef unsigned long long u64;

__device__ __forceinline__ float tanhm(float x) { float y; asm("tanh.approx.f32 %0, %1;" : "=f"(y) : "f"(x)); return y; }

__device__ __forceinline__ u64 pk2(float lo, float hi) { u64 r; asm("mov.b64 %0, {%1, %2};" : "=l"(r) : "f"(lo), "f"(hi)); return r; }
__device__ __forceinline__ void upk2(u64 v, float& lo, float& hi) { asm("mov.b64 {%0, %1}, %2;" : "=f"(lo), "=f"(hi) : "l"(v)); }
__device__ __forceinline__ u64 f2fma(u64 a, u64 b, u64 c) { u64 d; asm("fma.rn.f32x2 %0, %1, %2, %3;" : "=l"(d) : "l"(a), "l"(b), "l"(c)); return d; }
__device__ __forceinline__ u64 f2add(u64 a, u64 b) { u64 d; asm("add.rn.f32x2 %0, %1, %2;" : "=l"(d) : "l"(a), "l"(b)); return d; }
__device__ __forceinline__ uint32_t saddr(const void* p) {
    uint32_t a;
    asm("{ .reg .u64 t; cvta.to.shared.u64 t, %1; cvt.u32.u64 %0, t; }" : "=r"(a) : "l"(p));
    return a;
}
__device__ __forceinline__ void ldsv128(uint32_t a, u64& v0, u64& v1) {
    asm volatile("ld.volatile.shared.v2.b64 {%0, %1}, [%2];" : "=l"(v0), "=l"(v1) : "r"(a));
}
__device__ __forceinline__ void ldsv128f(uint32_t a, float& x, float& y, float& z, float& w) {
    asm volatile("ld.volatile.shared.v4.f32 {%0, %1, %2, %3}, [%4];" : "=f"(x), "=f"(y), "=f"(z), "=f"(w) : "r"(a));
}
__device__ __forceinline__ void stvolf32(uint32_t a, float v) { asm volatile("st.volatile.shared.f32 [%0], %1;" :: "r"(a), "f"(v)); }

__global__ void __launch_bounds__(128, 1) gru_seq_kernel(
    const float* __restrict__ x,        // [B, T, I]
    const int*   __restrict__ lengths,  // [B]
    const float* __restrict__ w_ih,     // [3H, I]
    const float* __restrict__ w_hh,     // [3H, H]
    const float* __restrict__ b_ih,     // [3H]
    const float* __restrict__ b_hh,     // [3H]
    const float* __restrict__ fc_w,     // [O, H]
    const float* __restrict__ fc_b,     // [O]
    float* __restrict__ out)            // [B, T, O]
{
    __shared__ __align__(16) float4 s_gx[2][CH][Hq];  // {pr, pz, pn, 0}
    __shared__ __align__(16) float s_h[2][CH][HPAD];  // h ring

    const int lane = threadIdx.x & 31;
    const int warp = threadIdx.x >> 5;
    const int b = blockIdx.x;
    const int L = lengths[b];

    const uint32_t hbase = saddr(&s_h[0][0][0]);
    const uint32_t gxbase = saddr(&s_gx[0][0][0]);

    if (warp == 0) {
        // ================= recurrence =================
        u64 wr[16], wz[16], wn[16];
        const float* rr = w_hh + lane * Hq;
        const float* rz = w_hh + (Hq + lane) * Hq;
        const float* rn = w_hh + (2 * Hq + lane) * Hq;
#pragma unroll
        for (int j = 0; j < 16; j++) {
            wr[j] = pk2(0.5f * rr[2 * j], 0.5f * rr[2 * j + 1]);   // /2 for sigmoid-as-tanh
            wz[j] = pk2(0.5f * rz[2 * j], 0.5f * rz[2 * j + 1]);
            wn[j] = pk2(rn[2 * j], rn[2 * j + 1]);                 // n: plain tanh
        }
        const u64 bhn_pk = pk2(b_hh[2 * Hq + lane], 0.0f);
        s_h[1][CH - 1][lane] = 0.0f;   // h_{-1} = 0 row
        float hk = 0.f;
        uint32_t hprev = hbase + ((1 * CH + (CH - 1)) * HPAD) * 4;

#define GRU_STEP(GXA, HROW)                                                    \
        {                                                                      \
            float pr, pz, pn, pd;                                              \
            ldsv128f((GXA), pr, pz, pn, pd);                                   \
            u64 hp[16];                                                        \
            _Pragma("unroll")                                                  \
            for (int j = 0; j < 8; j++)                                        \
                ldsv128(hprev + 16 * j, hp[2 * j], hp[2 * j + 1]);             \
            /* r-dot first: 4 accumulators, shallow chain */                   \
            u64 ar0 = pk2(pr, 0.f), ar1 = 0ull, ar2 = 0ull, ar3 = 0ull;        \
            _Pragma("unroll")                                                  \
            for (int j = 0; j < 16; j += 4) {                                  \
                ar0 = f2fma(wr[j], hp[j], ar0);                                \
                ar1 = f2fma(wr[j + 1], hp[j + 1], ar1);                        \
                ar2 = f2fma(wr[j + 2], hp[j + 2], ar2);                        \
                ar3 = f2fma(wr[j + 3], hp[j + 3], ar3);                        \
            }                                                                  \
            u64 sr = f2add(f2add(ar0, ar1), f2add(ar2, ar3));                  \
            float rl, rh; upk2(sr, rl, rh);                                    \
            float tr = tanhm(rl + rh);           /* MUFU in flight */          \
            /* n-dot (needed next-earliest) */                                 \
            u64 an0 = bhn_pk, an1 = 0ull;                                      \
            _Pragma("unroll")                                                  \
            for (int j = 0; j < 16; j += 2) {                                  \
                an0 = f2fma(wn[j], hp[j], an0);                                \
                an1 = f2fma(wn[j + 1], hp[j + 1], an1);                        \
            }                                                                  \
            u64 sn = f2add(an0, an1);                                          \
            float nl, nh; upk2(sn, nl, nh);                                    \
            float ns = nl + nh;                  /* = b_hhn + Wn.h */          \
            /* z-dot */                                                        \
            u64 az0 = pk2(pz, 0.f), az1 = 0ull;                                \
            _Pragma("unroll")                                                  \
            for (int j = 0; j < 16; j += 2) {                                  \
                az0 = f2fma(wz[j], hp[j], az0);                                \
                az1 = f2fma(wz[j + 1], hp[j + 1], az1);                        \
            }                                                                  \
            u64 sz = f2add(az0, az1);                                          \
            float zl, zh; upk2(sz, zl, zh);                                    \
            float tz = tanhm(zl + zh);                                         \
            /* arg_n = pn + r*ns,  r = 0.5*tr + 0.5 */                         \
            float ns2 = 0.5f * ns;                                             \
            float nsc = pn + ns2;                                              \
            float argn = fmaf(tr, ns2, nsc);                                   \
            float tn = tanhm(argn);                                            \
            /* h = (1-z)*n + z*h,  z = 0.5*tz + 0.5 (off-chain coeffs) */      \
            float zz = fmaf(0.5f, tz, 0.5f);                                   \
            float ca = 1.0f - zz;                                              \
            float cb = zz * hk;                                                \
            hk = fmaf(ca, tn, cb);                                             \
            stvolf32((HROW) + lane * 4, hk);                                   \
            hprev = (HROW);                                                    \
        }

        for (int c = 0; c < NCH; c++) {
            __syncthreads();
            int nst = L - c * CH;
            nst = nst < 0 ? 0 : (nst > CH ? CH : nst);
            uint32_t gxa = gxbase + ((c & 1) * CH * Hq) * 16 + lane * 16;
            uint32_t hrow = hbase + ((c & 1) * CH * HPAD) * 4;
            if (nst == CH) {
#pragma unroll 4
                for (int s = 0; s < CH; s++) {
                    GRU_STEP(gxa, hrow)
                    gxa += Hq * 16;
                    hrow += HPAD * 4;
                }
            } else {
#pragma unroll 1
                for (int s = 0; s < nst; s++) {
                    GRU_STEP(gxa, hrow)
                    gxa += Hq * 16;
                    hrow += HPAD * 4;
                }
            }
        }
        __syncthreads();
#undef GRU_STEP
    } else if (warp == 1) {
        // ================= FC output, one chunk behind =================
        for (int c = 0; c < NCH; c++) {
            __syncthreads();
            if (c > 0) {
                const int cp = c - 1;
                const int t = cp * CH + lane;
                float o0 = __ldg(fc_b + 0);
                float o1 = __ldg(fc_b + 1);
                if (t < L) {
                    const float* hr = &s_h[cp & 1][lane][0];
#pragma unroll
                    for (int j = 0; j < Hq; j++) {
                        float hv = hr[j];
                        o0 = fmaf(__ldg(fc_w + j), hv, o0);
                        o1 = fmaf(__ldg(fc_w + Hq + j), hv, o1);
                    }
                }
                float2 v = make_float2(o0, o1);
                *reinterpret_cast<float2*>(out + ((size_t)b * Tq + t) * Oq) = v;
            }
        }
        __syncthreads();
        {   // epilogue: last chunk
            const int cp = NCH - 1;
            const int t = cp * CH + lane;
            float o0 = __ldg(fc_b + 0);
            float o1 = __ldg(fc_b + 1);
            if (t < L) {
                const float* hr = &s_h[cp & 1][lane][0];
#pragma unroll
                for (int j = 0; j < Hq; j++) {
                    float hv = hr[j];
                    o0 = fmaf(__ldg(fc_w + j), hv, o0);
                    o1 = fmaf(__ldg(fc_w + Hq + j), hv, o1);
                }
            }
            float2 v = make_float2(o0, o1);
            *reinterpret_cast<float2*>(out + ((size_t)b * Tq + t) * Oq) = v;
        }
    } else {
        // ================= producers (warps 2,3), one chunk ahead =================
        float wiA[Iq], wiB[Iq], wiC[Iq];
#pragma unroll
        for (int i = 0; i < Iq; i++) {
            wiA[i] = 0.5f * w_ih[lane * Iq + i];          // pre-scaled for tanh-form
            wiB[i] = 0.5f * w_ih[(Hq + lane) * Iq + i];
            wiC[i] = w_ih[(2 * Hq + lane) * Iq + i];      // n: unscaled
        }
        const float biA = 0.5f * (b_ih[lane] + b_hh[lane]);
        const float biB = 0.5f * (b_ih[Hq + lane] + b_hh[Hq + lane]);
        const float biC = b_ih[2 * Hq + lane];
        const int s0 = (warp == 3) ? (CH / 2) : 0;

        // prologue: chunk 0
        {
            const float* xp = x + ((size_t)b * Tq + s0) * Iq;
#pragma unroll 1
            for (int s = 0; s < CH / 2; s++) {
                float xv[Iq];
#pragma unroll
                for (int i = 0; i < Iq; i++) xv[i] = xp[i];
                float gr = biA, gz = biB, gn = biC;
#pragma unroll
                for (int i = 0; i < Iq; i++) {
                    gr = fmaf(wiA[i], xv[i], gr);
                    gz = fmaf(wiB[i], xv[i], gz);
                    gn = fmaf(wiC[i], xv[i], gn);
                }
                s_gx[0][s0 + s][lane] = make_float4(gr, gz, gn, 0.0f);
                xp += Iq;
            }
        }
        for (int c = 0; c < NCH; c++) {
            __syncthreads();
            const int cc = c + 1;
            if (cc < NCH) {
                const float* xp = x + ((size_t)b * Tq + cc * CH + s0) * Iq;
#pragma unroll 1
                for (int s = 0; s < CH / 2; s++) {
                    float xv[Iq];
#pragma unroll
                    for (int i = 0; i < Iq; i++) xv[i] = xp[i];
                    float gr = biA, gz = biB, gn = biC;
#pragma unroll
                    for (int i = 0; i < Iq; i++) {
                        gr = fmaf(wiA[i], xv[i], gr);
                        gz = fmaf(wiB[i], xv[i], gz);
                        gn = fmaf(wiC[i], xv[i], gn);
                    }
                    s_gx[cc & 1][s0 + s][lane] = make_float4(gr, gz, gn, 0.0f);
                    xp += Iq;
                }
            }
        }
        __syncthreads();
    }
}

extern "C" void kernel_launch(void* const* d_in, const int* in_sizes, int n_in,
                              void* d_out, int out_size) {
    const float* x       = (const float*)d_in[0];
    const int*   lengths = (const int*)d_in[1];
    const float* w_ih    = (const float*)d_in[2];
    const float* w_hh    = (const float*)d_in[3];
    const float* b_ih    = (const float*)d_in[4];
    const float* b_hh    = (const float*)d_in[5];
    const float* fc_w    = (const float*)d_in[6];
    const float* fc_b    = (const float*)d_in[7];
    float* out = (float*)d_out;

    gru_seq_kernel<<<Bq, 128>>>(x, lengths, w_ih, w_hh, b_ih, b_hh, fc_w, fc_b, out);
}

// round 7
// speedup vs baseline: 1.8222x; 1.0084x over previous
#include <cuda_runtime.h>
#include <cuda_fp16.h>
#include <cstdint>

// GRU: B=128, T=4096, I=6, H=32, O=2. One CTA per sequence, 4 warps:
//   warp 0: full recurrence (critical path), fp16x2 dot products (HFMA2 rt=2)
//   warp 1: FC output, one chunk behind (reads exact f32 h ring)
//   warps 2,3: gx producers, one chunk ahead (f32)
// Activations: MUFU tanh.approx; sigmoid(v) = 0.5 + 0.5*tanh(v/2), the /2
// folded into pre-scaled weights / producer outputs.
// h is stored twice per step: f16 (for next step's fp16 dots) and f32 (for
// the FC warp, keeping the output projection exact). fp16 dot error (~1e-3/step)
// is damped ~100x by the GRU gates (measured R2 vs R6).

#define Bq 128
#define Tq 4096
#define Iq 6
#define Hq 32
#define Oq 2
#define CH 32
#define NCH (Tq / CH)
#define HPAD 36   // f32 h ring rows: 144B

__device__ __forceinline__ float tanhm(float x) { float y; asm("tanh.approx.f32 %0, %1;" : "=f"(y) : "f"(x)); return y; }

__device__ __forceinline__ uint32_t saddr(const void* p) {
    uint32_t a;
    asm("{ .reg .u64 t; cvta.to.shared.u64 t, %1; cvt.u32.u64 %0, t; }" : "=r"(a) : "l"(p));
    return a;
}
__device__ __forceinline__ void ldsv128u(uint32_t a, uint32_t& x, uint32_t& y, uint32_t& z, uint32_t& w) {
    asm volatile("ld.volatile.shared.v4.b32 {%0, %1, %2, %3}, [%4];" : "=r"(x), "=r"(y), "=r"(z), "=r"(w) : "r"(a));
}
__device__ __forceinline__ void ldsv128f(uint32_t a, float& x, float& y, float& z, float& w) {
    asm volatile("ld.volatile.shared.v4.f32 {%0, %1, %2, %3}, [%4];" : "=f"(x), "=f"(y), "=f"(z), "=f"(w) : "r"(a));
}
__device__ __forceinline__ void stv16(uint32_t a, unsigned short v) {
    asm volatile("st.volatile.shared.u16 [%0], %1;" :: "r"(a), "h"(v));
}
__device__ __forceinline__ void sts32p(uint32_t a, float v) {
    asm volatile("st.shared.f32 [%0], %1;" :: "r"(a), "f"(v));
}
__device__ __forceinline__ __half2 u2h2(uint32_t u) { __half2 h; asm("mov.b32 %0, %1;" : "=r"(*(uint32_t*)&h) : "r"(u)); return h; }

__global__ void __launch_bounds__(128, 1) gru_seq_kernel(
    const float* __restrict__ x,        // [B, T, I]
    const int*   __restrict__ lengths,  // [B]
    const float* __restrict__ w_ih,     // [3H, I]
    const float* __restrict__ w_hh,     // [3H, H]
    const float* __restrict__ b_ih,     // [3H]
    const float* __restrict__ b_hh,     // [3H]
    const float* __restrict__ fc_w,     // [O, H]
    const float* __restrict__ fc_b,     // [O]
    float* __restrict__ out)            // [B, T, O]
{
    __shared__ __align__(16) float4 s_gx[2][CH][Hq];   // {pr, pz, pn, 0}
    __shared__ __align__(16) float  s_h[2][CH][HPAD];  // f32 h ring (for FC)
    __shared__ __align__(16) __half s_h16[2][CH][Hq];  // f16 h ring (for dots)

    const int lane = threadIdx.x & 31;
    const int warp = threadIdx.x >> 5;
    const int b = blockIdx.x;
    const int L = lengths[b];

    const uint32_t hbase   = saddr(&s_h[0][0][0]);
    const uint32_t h16base = saddr(&s_h16[0][0][0]);
    const uint32_t gxbase  = saddr(&s_gx[0][0][0]);

    if (warp == 0) {
        // ================= recurrence =================
        __half2 wr[16], wz[16], wn[16];
        const float* rr = w_hh + lane * Hq;
        const float* rz = w_hh + (Hq + lane) * Hq;
        const float* rn = w_hh + (2 * Hq + lane) * Hq;
#pragma unroll
        for (int j = 0; j < 16; j++) {
            wr[j] = __floats2half2_rn(0.5f * rr[2 * j], 0.5f * rr[2 * j + 1]);  // /2: sigmoid-as-tanh
            wz[j] = __floats2half2_rn(0.5f * rz[2 * j], 0.5f * rz[2 * j + 1]);
            wn[j] = __floats2half2_rn(rn[2 * j], rn[2 * j + 1]);                // n: plain tanh
        }
        const float bhn = b_hh[2 * Hq + lane];
        // initial h_{-1} = 0 row (f16 ring only; FC never reads it)
        stv16(h16base + ((1 * CH + (CH - 1)) * Hq + lane) * 2, (unsigned short)0);
        float hk = 0.f;
        uint32_t hprev16 = h16base + ((1 * CH + (CH - 1)) * Hq) * 2;

#define GRU_STEP(GXA, H16ROW, HROWF)                                           \
        {                                                                      \
            float pr, pz, pn, pd;                                              \
            ldsv128f((GXA), pr, pz, pn, pd);                                   \
            uint32_t u[16];                                                    \
            ldsv128u(hprev16 +  0, u[0],  u[1],  u[2],  u[3]);                 \
            ldsv128u(hprev16 + 16, u[4],  u[5],  u[6],  u[7]);                 \
            ldsv128u(hprev16 + 32, u[8],  u[9],  u[10], u[11]);                \
            ldsv128u(hprev16 + 48, u[12], u[13], u[14], u[15]);                \
            __half2 h2[16];                                                    \
            _Pragma("unroll")                                                  \
            for (int j = 0; j < 16; j++) h2[j] = u2h2(u[j]);                   \
            const __half2 hz = __float2half2_rn(0.f);                          \
            __half2 ar0 = hz, ar1 = hz, ar2 = hz, ar3 = hz;                    \
            __half2 az0 = hz, az1 = hz, az2 = hz, az3 = hz;                    \
            __half2 an0 = hz, an1 = hz, an2 = hz, an3 = hz;                    \
            _Pragma("unroll")                                                  \
            for (int j = 0; j < 16; j += 4) {      /* r first: longest tail */ \
                ar0 = __hfma2(wr[j],     h2[j],     ar0);                      \
                ar1 = __hfma2(wr[j + 1], h2[j + 1], ar1);                      \
                ar2 = __hfma2(wr[j + 2], h2[j + 2], ar2);                      \
                ar3 = __hfma2(wr[j + 3], h2[j + 3], ar3);                      \
            }                                                                  \
            _Pragma("unroll")                                                  \
            for (int j = 0; j < 16; j += 4) {      /* z second */              \
                az0 = __hfma2(wz[j],     h2[j],     az0);                      \
                az1 = __hfma2(wz[j + 1], h2[j + 1], az1);                      \
                az2 = __hfma2(wz[j + 2], h2[j + 2], az2);                      \
                az3 = __hfma2(wz[j + 3], h2[j + 3], az3);                      \
            }                                                                  \
            _Pragma("unroll")                                                  \
            for (int j = 0; j < 16; j += 4) {      /* n last */                \
                an0 = __hfma2(wn[j],     h2[j],     an0);                      \
                an1 = __hfma2(wn[j + 1], h2[j + 1], an1);                      \
                an2 = __hfma2(wn[j + 2], h2[j + 2], an2);                      \
                an3 = __hfma2(wn[j + 3], h2[j + 3], an3);                      \
            }                                                                  \
            __half2 sr = __hadd2(__hadd2(ar0, ar1), __hadd2(ar2, ar3));        \
            float2 fr = __half22float2(sr);                                    \
            float tr = tanhm(fr.x + fr.y + pr);                                \
            __half2 sz = __hadd2(__hadd2(az0, az1), __hadd2(az2, az3));        \
            float2 fz = __half22float2(sz);                                    \
            float tz = tanhm(fz.x + fz.y + pz);                                \
            __half2 sn = __hadd2(__hadd2(an0, an1), __hadd2(an2, an3));        \
            float2 fn = __half22float2(sn);                                    \
            float ns = fn.x + fn.y + bhn;                                      \
            float ns2 = 0.5f * ns;                                             \
            float nsc = pn + ns2;                                              \
            float argn = fmaf(tr, ns2, nsc);     /* xn + r*hn */               \
            float tn = tanhm(argn);                                            \
            float zz = fmaf(0.5f, tz, 0.5f);                                   \
            float ca = 1.0f - zz;                                              \
            float cb = zz * hk;                                                \
            hk = fmaf(ca, tn, cb);               /* h_new */                   \
            stv16((H16ROW) + lane * 2, __half_as_ushort(__float2half_rn(hk))); \
            sts32p((HROWF) + lane * 4, hk);      /* f32 copy for FC */         \
            hprev16 = (H16ROW);                                                \
        }

        for (int c = 0; c < NCH; c++) {
            __syncthreads();
            int nst = L - c * CH;
            nst = nst < 0 ? 0 : (nst > CH ? CH : nst);
            uint32_t gxa = gxbase + ((c & 1) * CH * Hq) * 16 + lane * 16;
            uint32_t h16row = h16base + ((c & 1) * CH * Hq) * 2;
            uint32_t hrowf = hbase + ((c & 1) * CH * HPAD) * 4;
            if (nst == CH) {
#pragma unroll 4
                for (int s = 0; s < CH; s++) {
                    GRU_STEP(gxa, h16row, hrowf)
                    gxa += Hq * 16;
                    h16row += Hq * 2;
                    hrowf += HPAD * 4;
                }
            } else {
#pragma unroll 1
                for (int s = 0; s < nst; s++) {
                    GRU_STEP(gxa, h16row, hrowf)
                    gxa += Hq * 16;
                    h16row += Hq * 2;
                    hrowf += HPAD * 4;
                }
            }
        }
        __syncthreads();
#undef GRU_STEP
    } else if (warp == 1) {
        // ================= FC output, one chunk behind =================
        for (int c = 0; c < NCH; c++) {
            __syncthreads();
            if (c > 0) {
                const int cp = c - 1;
                const int t = cp * CH + lane;
                float o0 = __ldg(fc_b + 0);
                float o1 = __ldg(fc_b + 1);
                if (t < L) {
                    const float* hr = &s_h[cp & 1][lane][0];
#pragma unroll
                    for (int j = 0; j < Hq; j++) {
                        float hv = hr[j];
                        o0 = fmaf(__ldg(fc_w + j), hv, o0);
                        o1 = fmaf(__ldg(fc_w + Hq + j), hv, o1);
                    }
                }
                float2 v = make_float2(o0, o1);
                *reinterpret_cast<float2*>(out + ((size_t)b * Tq + t) * Oq) = v;
            }
        }
        __syncthreads();
        {   // epilogue: last chunk
            const int cp = NCH - 1;
            const int t = cp * CH + lane;
            float o0 = __ldg(fc_b + 0);
            float o1 = __ldg(fc_b + 1);
            if (t < L) {
                const float* hr = &s_h[cp & 1][lane][0];
#pragma unroll
                for (int j = 0; j < Hq; j++) {
                    float hv = hr[j];
                    o0 = fmaf(__ldg(fc_w + j), hv, o0);
                    o1 = fmaf(__ldg(fc_w + Hq + j), hv, o1);
                }
            }
            float2 v = make_float2(o0, o1);
            *reinterpret_cast<float2*>(out + ((size_t)b * Tq + t) * Oq) = v;
        }
    } else {
        // ================= producers (warps 2,3), one chunk ahead =================
        float wiA[Iq], wiB[Iq], wiC[Iq];
#pragma unroll
        for (int i = 0; i < Iq; i++) {
            wiA[i] = 0.5f * w_ih[lane * Iq + i];          // pre-scaled for tanh-form
            wiB[i] = 0.5f * w_ih[(Hq + lane) * Iq + i];
            wiC[i] = w_ih[(2 * Hq + lane) * Iq + i];      // n: unscaled
        }
        const float biA = 0.5f * (b_ih[lane] + b_hh[lane]);
        const float biB = 0.5f * (b_ih[Hq + lane] + b_hh[Hq + lane]);
        const float biC = b_ih[2 * Hq + lane];
        const int s0 = (warp == 3) ? (CH / 2) : 0;

        // prologue: chunk 0
        {
            const float* xp = x + ((size_t)b * Tq + s0) * Iq;
#pragma unroll 1
            for (int s = 0; s < CH / 2; s++) {
                float xv[Iq];
#pragma unroll
                for (int i = 0; i < Iq; i++) xv[i] = xp[i];
                float gr = biA, gz = biB, gn = biC;
#pragma unroll
                for (int i = 0; i < Iq; i++) {
                    gr = fmaf(wiA[i], xv[i], gr);
                    gz = fmaf(wiB[i], xv[i], gz);
                    gn = fmaf(wiC[i], xv[i], gn);
                }
                s_gx[0][s0 + s][lane] = make_float4(gr, gz, gn, 0.0f);
                xp += Iq;
            }
        }
        for (int c = 0; c < NCH; c++) {
            __syncthreads();
            const int cc = c + 1;
            if (cc < NCH) {
                const float* xp = x + ((size_t)b * Tq + cc * CH + s0) * Iq;
#pragma unroll 1
                for (int s = 0; s < CH / 2; s++) {
                    float xv[Iq];
#pragma unroll
                    for (int i = 0; i < Iq; i++) xv[i] = xp[i];
                    float gr = biA, gz = biB, gn = biC;
#pragma unroll
                    for (int i = 0; i < Iq; i++) {
                        gr = fmaf(wiA[i], xv[i], gr);
                        gz = fmaf(wiB[i], xv[i], gz);
                        gn = fmaf(wiC[i], xv[i], gn);
                    }
                    s_gx[cc & 1][s0 + s][lane] = make_float4(gr, gz, gn, 0.0f);
                    xp += Iq;
                }
            }
        }
        __syncthreads();
    }
}

extern "C" void kernel_launch(void* const* d_in, const int* in_sizes, int n_in,
                              void* d_out, int out_size) {
    const float* x       = (const float*)d_in[0];
    const int*   lengths = (const int*)d_in[1];
    const float* w_ih    = (const float*)d_in[2];
    const float* w_hh    = (const float*)d_in[3];
    const float* b_ih    = (const float*)d_in[4];
    const float* b_hh    = (const float*)d_in[5];
    const float* fc_w    = (const float*)d_in[6];
    const float* fc_b    = (const float*)d_in[7];
    float* out = (float*)d_out;

    gru_seq_kernel<<<Bq, 128>>>(x, lengths, w_ih, w_hh, b_ih, b_hh, fc_w, fc_b, out);
}

// round 9
// speedup vs baseline: 1.9059x; 1.0459x over previous
#include <cuda_runtime.h>
#include <cuda_fp16.h>
#include <cstdint>

// GRU: B=128, T=4096, I=6, H=32, O=2. One CTA per sequence, 4 warps:
//   warp 0: full recurrence. fp16x2 dots (HFMA2), f32 activations/update.
//   warp 1: FC output, one chunk behind (reads exact f32 h ring)
//   warps 2,3: gx producers, one chunk ahead (f32)
// Gate algebra (0.5 factors folded into weights/producers):
//   r = 0.5 + 0.5*t_r, t_r = tanh_f32(rdot16 + pr) ;  z analogous
//   ns = (0.5*Wn).h (f16 dot) + 0.5*bhn (f32) ; argn = pn + ns + t_r*ns
//   h  = (1-z)*n + z*h  (f32) ; stored f16 (recurrence) + f32 (FC)
// f16 is confined to the MACs: R8 showed f16 activations/state-update/output
// blow the error budget (6e-3); this split measured 4.9e-5 in R7.

#define Bq 128
#define Tq 4096
#define Iq 6
#define Hq 32
#define Oq 2
#define CH 32
#define NCH (Tq / CH)
#define HPAD 36   // f32 h ring rows: 144B

__device__ __forceinline__ float tanhm(float x) { float y; asm("tanh.approx.f32 %0, %1;" : "=f"(y) : "f"(x)); return y; }

__device__ __forceinline__ uint32_t saddr(const void* p) {
    uint32_t a;
    asm("{ .reg .u64 t; cvta.to.shared.u64 t, %1; cvt.u32.u64 %0, t; }" : "=r"(a) : "l"(p));
    return a;
}
__device__ __forceinline__ void ldsv128u(uint32_t a, uint32_t& x, uint32_t& y, uint32_t& z, uint32_t& w) {
    asm volatile("ld.volatile.shared.v4.b32 {%0, %1, %2, %3}, [%4];" : "=r"(x), "=r"(y), "=r"(z), "=r"(w) : "r"(a));
}
__device__ __forceinline__ void stv16(uint32_t a, unsigned short v) {
    asm volatile("st.volatile.shared.u16 [%0], %1;" :: "r"(a), "h"(v));
}
__device__ __forceinline__ void sts32p(uint32_t a, float v) {
    asm volatile("st.shared.f32 [%0], %1;" :: "r"(a), "f"(v));
}
__device__ __forceinline__ __half2 u2h2(uint32_t u) { __half2 h; *(uint32_t*)&h = u; return h; }

__global__ void __launch_bounds__(128, 1) gru_seq_kernel(
    const float* __restrict__ x,        // [B, T, I]
    const int*   __restrict__ lengths,  // [B]
    const float* __restrict__ w_ih,     // [3H, I]
    const float* __restrict__ w_hh,     // [3H, H]
    const float* __restrict__ b_ih,     // [3H]
    const float* __restrict__ b_hh,     // [3H]
    const float* __restrict__ fc_w,     // [O, H]
    const float* __restrict__ fc_b,     // [O]
    float* __restrict__ out)            // [B, T, O]
{
    __shared__ __align__(16) float4 s_gx[2][CH][Hq];   // {pr, pz, pn, 0}
    __shared__ __align__(16) float  s_h[2][CH][HPAD];  // f32 h ring (for FC)
    __shared__ __align__(16) __half s_h16[2][CH][Hq];  // f16 h ring (for dots)

    const int lane = threadIdx.x & 31;
    const int warp = threadIdx.x >> 5;
    const int b = blockIdx.x;
    const int L = lengths[b];

    const uint32_t hbase   = saddr(&s_h[0][0][0]);
    const uint32_t h16base = saddr(&s_h16[0][0][0]);

    if (warp == 0) {
        // ================= recurrence =================
        __half2 wr[16], wz[16], wn[16];
        const float* rr = w_hh + lane * Hq;
        const float* rz = w_hh + (Hq + lane) * Hq;
        const float* rn = w_hh + (2 * Hq + lane) * Hq;
#pragma unroll
        for (int j = 0; j < 16; j++) {
            wr[j] = __floats2half2_rn(0.5f * rr[2 * j], 0.5f * rr[2 * j + 1]);  // sigmoid-as-tanh /2
            wz[j] = __floats2half2_rn(0.5f * rz[2 * j], 0.5f * rz[2 * j + 1]);
            wn[j] = __floats2half2_rn(0.5f * rn[2 * j], 0.5f * rn[2 * j + 1]);  // gate folding /2
        }
        const float bhn05 = 0.5f * b_hh[2 * Hq + lane];
        stv16(h16base + ((1 * CH + (CH - 1)) * Hq + lane) * 2, (unsigned short)0);  // h_{-1}=0
        float hk = 0.f;
        uint32_t hprev16 = h16base + ((1 * CH + (CH - 1)) * Hq) * 2;

#define GRU_STEP(CBUF, S, H16ROW, HROWF)                                       \
        {                                                                      \
            float4 gx = s_gx[CBUF][S][lane];        /* non-volatile: hoistable */ \
            uint32_t u[16];                                                    \
            ldsv128u(hprev16 +  0, u[0],  u[1],  u[2],  u[3]);                 \
            ldsv128u(hprev16 + 16, u[4],  u[5],  u[6],  u[7]);                 \
            ldsv128u(hprev16 + 32, u[8],  u[9],  u[10], u[11]);                \
            ldsv128u(hprev16 + 48, u[12], u[13], u[14], u[15]);                \
            __half2 h2[16];                                                    \
            _Pragma("unroll")                                                  \
            for (int j = 0; j < 16; j++) h2[j] = u2h2(u[j]);                   \
            const __half2 hz2 = __half2half2(__ushort_as_half((unsigned short)0)); \
            /* r-dot: 4 accumulators (chain ~ issue), earliest */              \
            __half2 ar0 = hz2, ar1 = hz2, ar2 = hz2, ar3 = hz2;                \
            _Pragma("unroll")                                                  \
            for (int j = 0; j < 16; j += 4) {                                  \
                ar0 = __hfma2(wr[j],     h2[j],     ar0);                      \
                ar1 = __hfma2(wr[j + 1], h2[j + 1], ar1);                      \
                ar2 = __hfma2(wr[j + 2], h2[j + 2], ar2);                      \
                ar3 = __hfma2(wr[j + 3], h2[j + 3], ar3);                      \
            }                                                                  \
            __half2 sr = __hadd2(__hadd2(ar0, ar1), __hadd2(ar2, ar3));        \
            /* z,n dots: 2 accumulators each, latency hidden under r tail */   \
            __half2 az0 = hz2, az1 = hz2;                                      \
            _Pragma("unroll")                                                  \
            for (int j = 0; j < 16; j += 2) {                                  \
                az0 = __hfma2(wz[j],     h2[j],     az0);                      \
                az1 = __hfma2(wz[j + 1], h2[j + 1], az1);                      \
            }                                                                  \
            __half2 an0 = hz2, an1 = hz2;                                      \
            _Pragma("unroll")                                                  \
            for (int j = 0; j < 16; j += 2) {                                  \
                an0 = __hfma2(wn[j],     h2[j],     an0);                      \
                an1 = __hfma2(wn[j + 1], h2[j + 1], an1);                      \
            }                                                                  \
            __half2 sz = __hadd2(az0, az1);                                    \
            /* packed cross-half reduce for r,z together */                    \
            __half2 pa = __lows2half2(sr, sz);                                 \
            __half2 pb = __highs2half2(sr, sz);                                \
            __half2 srz = __hadd2(pa, pb);          /* {rdot, zdot} */         \
            float2 frz = __half22float2(srz);                                  \
            float tr = tanhm(frz.x + gx.x);                                    \
            float tz = tanhm(frz.y + gx.y);                                    \
            __half2 sn = __hadd2(an0, an1);                                    \
            float2 fn = __half22float2(sn);                                    \
            float ns = fn.x + fn.y + bhn05;         /* 0.5*(Wn.h + bhn) */     \
            float nsc = gx.z + ns;                                             \
            float argn = fmaf(tr, ns, nsc);         /* xn + r*hn */            \
            float tn = tanhm(argn);                                            \
            float zz = fmaf(0.5f, tz, 0.5f);                                   \
            float cb = zz * hk;                                                \
            float ca = 1.0f - zz;                                              \
            hk = fmaf(ca, tn, cb);                  /* h_new (f32) */          \
            stv16((H16ROW) + lane * 2, __half_as_ushort(__float2half_rn(hk))); \
            sts32p((HROWF) + lane * 4, hk);         /* exact copy for FC */    \
            hprev16 = (H16ROW);                                                \
        }

        for (int c = 0; c < NCH; c++) {
            __syncthreads();
            int nst = L - c * CH;
            nst = nst < 0 ? 0 : (nst > CH ? CH : nst);
            const int cb1 = c & 1;
            uint32_t h16row = h16base + (cb1 * CH * Hq) * 2;
            uint32_t hrowf = hbase + (cb1 * CH * HPAD) * 4;
            if (nst == CH) {
#pragma unroll 4
                for (int s = 0; s < CH; s++) {
                    GRU_STEP(cb1, s, h16row, hrowf)
                    h16row += Hq * 2;
                    hrowf += HPAD * 4;
                }
            } else {
#pragma unroll 1
                for (int s = 0; s < nst; s++) {
                    GRU_STEP(cb1, s, h16row, hrowf)
                    h16row += Hq * 2;
                    hrowf += HPAD * 4;
                }
            }
        }
        __syncthreads();
#undef GRU_STEP
    } else if (warp == 1) {
        // ================= FC output, one chunk behind =================
        for (int c = 0; c < NCH; c++) {
            __syncthreads();
            if (c > 0) {
                const int cp = c - 1;
                const int t = cp * CH + lane;
                float o0 = __ldg(fc_b + 0);
                float o1 = __ldg(fc_b + 1);
                if (t < L) {
                    const float* hr = &s_h[cp & 1][lane][0];
#pragma unroll
                    for (int j = 0; j < Hq; j++) {
                        float hv = hr[j];
                        o0 = fmaf(__ldg(fc_w + j), hv, o0);
                        o1 = fmaf(__ldg(fc_w + Hq + j), hv, o1);
                    }
                }
                float2 v = make_float2(o0, o1);
                *reinterpret_cast<float2*>(out + ((size_t)b * Tq + t) * Oq) = v;
            }
        }
        __syncthreads();
        {   // epilogue: last chunk
            const int cp = NCH - 1;
            const int t = cp * CH + lane;
            float o0 = __ldg(fc_b + 0);
            float o1 = __ldg(fc_b + 1);
            if (t < L) {
                const float* hr = &s_h[cp & 1][lane][0];
#pragma unroll
                for (int j = 0; j < Hq; j++) {
                    float hv = hr[j];
                    o0 = fmaf(__ldg(fc_w + j), hv, o0);
                    o1 = fmaf(__ldg(fc_w + Hq + j), hv, o1);
                }
            }
            float2 v = make_float2(o0, o1);
            *reinterpret_cast<float2*>(out + ((size_t)b * Tq + t) * Oq) = v;
        }
    } else {
        // ================= producers (warps 2,3), one chunk ahead =================
        float wiA[Iq], wiB[Iq], wiC[Iq];
#pragma unroll
        for (int i = 0; i < Iq; i++) {
            wiA[i] = 0.5f * w_ih[lane * Iq + i];          // pre-scaled for tanh-form
            wiB[i] = 0.5f * w_ih[(Hq + lane) * Iq + i];
            wiC[i] = w_ih[(2 * Hq + lane) * Iq + i];      // pn: unscaled
        }
        const float biA = 0.5f * (b_ih[lane] + b_hh[lane]);
        const float biB = 0.5f * (b_ih[Hq + lane] + b_hh[Hq + lane]);
        const float biC = b_ih[2 * Hq + lane];
        const int s0 = (warp == 3) ? (CH / 2) : 0;

        // prologue: chunk 0
        {
            const float* xp = x + ((size_t)b * Tq + s0) * Iq;
#pragma unroll 1
            for (int s = 0; s < CH / 2; s++) {
                float xv[Iq];
#pragma unroll
                for (int i = 0; i < Iq; i++) xv[i] = xp[i];
                float gr = biA, gz = biB, gn = biC;
#pragma unroll
                for (int i = 0; i < Iq; i++) {
                    gr = fmaf(wiA[i], xv[i], gr);
                    gz = fmaf(wiB[i], xv[i], gz);
                    gn = fmaf(wiC[i], xv[i], gn);
                }
                s_gx[0][s0 + s][lane] = make_float4(gr, gz, gn, 0.0f);
                xp += Iq;
            }
        }
        for (int c = 0; c < NCH; c++) {
            __syncthreads();
            const int cc = c + 1;
            if (cc < NCH) {
                const float* xp = x + ((size_t)b * Tq + cc * CH + s0) * Iq;
#pragma unroll 1
                for (int s = 0; s < CH / 2; s++) {
                    float xv[Iq];
#pragma unroll
                    for (int i = 0; i < Iq; i++) xv[i] = xp[i];
                    float gr = biA, gz = biB, gn = biC;
#pragma unroll
                    for (int i = 0; i < Iq; i++) {
                        gr = fmaf(wiA[i], xv[i], gr);
                        gz = fmaf(wiB[i], xv[i], gz);
                        gn = fmaf(wiC[i], xv[i], gn);
                    }
                    s_gx[cc & 1][s0 + s][lane] = make_float4(gr, gz, gn, 0.0f);
                    xp += Iq;
                }
            }
        }
        __syncthreads();
    }
}

extern "C" void kernel_launch(void* const* d_in, const int* in_sizes, int n_in,
                              void* d_out, int out_size) {
    const float* x       = (const float*)d_in[0];
    const int*   lengths = (const int*)d_in[1];
    const float* w_ih    = (const float*)d_in[2];
    const float* w_hh    = (const float*)d_in[3];
    const float* b_ih    = (const float*)d_in[4];
    const float* b_hh    = (const float*)d_in[5];
    const float* fc_w    = (const float*)d_in[6];
    const float* fc_b    = (const float*)d_in[7];
    float* out = (float*)d_out;

    gru_seq_kernel<<<Bq, 128>>>(x, lengths, w_ih, w_hh, b_ih, b_hh, fc_w, fc_b, out);
}

// round 10
// speedup vs baseline: 1.9788x; 1.0383x over previous
#include <cuda_runtime.h>
#include <cuda_fp16.h>
#include <cstdint>

// GRU: B=128, T=4096, I=6, H=32, O=2. One CTA per sequence, 4 warps:
//   warp 0: recurrence via tensor-core GEMV: y(96) = W_hh(96x32) . h(32)
//           as 12x mma.sync.m16n8k16 (f16 in, f32 accum), f32 activations.
//   warp 1: FC output, one chunk behind (exact f32 h ring)
//   warps 2,3: gx producers, one chunk ahead (f32)
// Layout trick: B fragments are loaded IDENTICALLY in all lanes (ignoring
// groupID), so all 8 columns of D hold the same y. Lane t then owns hidden
// unit u = gid + 8*(tig&1) + 16*(tig>>1) and reads r/z/n from its OWN
// C-fragment regs (c0 for tig even-row, c2 for +8 row) — no shuffles.
// Gate algebra (0.5 folded into weights/producers, as R9):
//   r = 0.5+0.5*tanh(pr + 0.5*Wr.h) ; z analogous
//   ns = 0.5*(Wn.h + bhn) (bias folded into n-tile C-init)
//   argn = pn + ns + t_r*ns ; h = (1-z)*n + z*h  (all f32)

#define Bq 128
#define Tq 4096
#define Iq 6
#define Hq 32
#define Oq 2
#define CH 32
#define NCH (Tq / CH)
#define HPAD 36   // f32 h ring rows: 144B

__device__ __forceinline__ float tanhm(float x) { float y; asm("tanh.approx.f32 %0, %1;" : "=f"(y) : "f"(x)); return y; }

__device__ __forceinline__ uint32_t saddr(const void* p) {
    uint32_t a;
    asm("{ .reg .u64 t; cvta.to.shared.u64 t, %1; cvt.u32.u64 %0, t; }" : "=r"(a) : "l"(p));
    return a;
}
__device__ __forceinline__ uint32_t ldv32(uint32_t a) {
    uint32_t v; asm volatile("ld.volatile.shared.b32 %0, [%1];" : "=r"(v) : "r"(a)); return v;
}
__device__ __forceinline__ void stv16(uint32_t a, unsigned short v) {
    asm volatile("st.volatile.shared.u16 [%0], %1;" :: "r"(a), "h"(v));
}
__device__ __forceinline__ void sts32p(uint32_t a, float v) {
    asm volatile("st.shared.f32 [%0], %1;" :: "r"(a), "f"(v));
}
__device__ __forceinline__ uint32_t packh2(float lo, float hi) {
    __half2 h = __floats2half2_rn(lo, hi);
    return *(uint32_t*)&h;
}

// D (fresh) = A*B + Cq (external C quad)
#define MMA_LD(D, A, B0, B1, C0, C1, C2, C3)                                   \
    asm volatile(                                                              \
        "mma.sync.aligned.m16n8k16.row.col.f32.f16.f16.f32 "                   \
        "{%0,%1,%2,%3}, {%4,%5,%6,%7}, {%8,%9}, {%10,%11,%12,%13};"            \
        : "=f"((D)[0]), "=f"((D)[1]), "=f"((D)[2]), "=f"((D)[3])               \
        : "r"((A)[0]), "r"((A)[1]), "r"((A)[2]), "r"((A)[3]),                  \
          "r"(B0), "r"(B1),                                                    \
          "f"(C0), "f"(C1), "f"(C2), "f"(C3))

// D += A*B (in place)
#define MMA_ACC(D, A, B0, B1)                                                  \
    asm volatile(                                                              \
        "mma.sync.aligned.m16n8k16.row.col.f32.f16.f16.f32 "                   \
        "{%0,%1,%2,%3}, {%4,%5,%6,%7}, {%8,%9}, {%0,%1,%2,%3};"                \
        : "+f"((D)[0]), "+f"((D)[1]), "+f"((D)[2]), "+f"((D)[3])               \
        : "r"((A)[0]), "r"((A)[1]), "r"((A)[2]), "r"((A)[3]),                  \
          "r"(B0), "r"(B1))

__global__ void __launch_bounds__(128, 1) gru_seq_kernel(
    const float* __restrict__ x,        // [B, T, I]
    const int*   __restrict__ lengths,  // [B]
    const float* __restrict__ w_ih,     // [3H, I]
    const float* __restrict__ w_hh,     // [3H, H]  (96 x 32 row-major)
    const float* __restrict__ b_ih,     // [3H]
    const float* __restrict__ b_hh,     // [3H]
    const float* __restrict__ fc_w,     // [O, H]
    const float* __restrict__ fc_b,     // [O]
    float* __restrict__ out)            // [B, T, O]
{
    __shared__ __align__(16) float4 s_gx[2][CH][Hq];   // {pr, pz, pn, 0} by hidden unit
    __shared__ __align__(16) float  s_h[2][CH][HPAD];  // f32 h ring (for FC)
    __shared__ __align__(16) __half s_h16[2][CH][Hq];  // f16 h ring (64B rows)

    const int lane = threadIdx.x & 31;
    const int warp = threadIdx.x >> 5;
    const int b = blockIdx.x;
    const int L = lengths[b];

    const uint32_t hbase   = saddr(&s_h[0][0][0]);
    const uint32_t h16base = saddr(&s_h16[0][0][0]);

    if (warp == 0) {
        // ================= recurrence (tensor-core GEMV) =================
        const int gid = lane >> 2;          // groupID (0..7)
        const int tig = lane & 3;           // thread-in-group
        const int u = gid + ((tig & 1) << 3) + ((tig & 2) << 3);  // owned hidden unit
        const bool p0 = (tig == 0), p1 = (tig == 1), p2 = (tig == 2);

        // A fragments: af[mt][kt][4]; tiles m0,m1 = r rows 0..31; m2,m3 = z; m4,m5 = n.
        uint32_t af[6][2][4];
#pragma unroll
        for (int mt = 0; mt < 6; mt++)
#pragma unroll
            for (int kt = 0; kt < 2; kt++) {
                const int r0 = mt * 16 + gid;
                const int r1 = r0 + 8;
                const int c0 = kt * 16 + 2 * tig;
                af[mt][kt][0] = packh2(0.5f * w_hh[r0 * Hq + c0],     0.5f * w_hh[r0 * Hq + c0 + 1]);
                af[mt][kt][1] = packh2(0.5f * w_hh[r1 * Hq + c0],     0.5f * w_hh[r1 * Hq + c0 + 1]);
                af[mt][kt][2] = packh2(0.5f * w_hh[r0 * Hq + c0 + 8], 0.5f * w_hh[r0 * Hq + c0 + 9]);
                af[mt][kt][3] = packh2(0.5f * w_hh[r1 * Hq + c0 + 8], 0.5f * w_hh[r1 * Hq + c0 + 9]);
            }
        // n-tile bias C-quads (0.5*bhn by row), r/z use zero quad
        const float bn4a = 0.5f * b_hh[2 * Hq + gid];        // m4 row gid
        const float bn4b = 0.5f * b_hh[2 * Hq + gid + 8];    // m4 row gid+8
        const float bn5a = 0.5f * b_hh[2 * Hq + 16 + gid];   // m5 row gid
        const float bn5b = 0.5f * b_hh[2 * Hq + 24 + gid];   // m5 row gid+8
        const float fz = 0.0f;

        stv16(h16base + ((1 * CH + (CH - 1)) * Hq + u) * 2, (unsigned short)0);  // h_{-1}=0
        float hk = 0.f;
        uint32_t hprev16 = h16base + ((1 * CH + (CH - 1)) * Hq) * 2;
        const uint32_t tig4 = tig * 4;

#define GRU_STEP(CBUF, S, H16ROW, HROWF)                                       \
        {                                                                      \
            float4 gx = s_gx[CBUF][S][u];                                      \
            /* B fragments: same in all lanes of a column group -> cols equal */ \
            uint32_t b0 = ldv32(hprev16 + tig4);          /* h[2tig..+1]   */  \
            uint32_t b1 = ldv32(hprev16 + 16 + tig4);     /* h[8+2tig..]   */  \
            uint32_t b2 = ldv32(hprev16 + 32 + tig4);     /* h[16+2tig..]  */  \
            uint32_t b3 = ldv32(hprev16 + 48 + tig4);     /* h[24+2tig..]  */  \
            float dR0[4], dR1[4], dZ0[4], dZ1[4], dN0[4], dN1[4];              \
            MMA_LD(dR0, af[0][0], b0, b1, fz, fz, fz, fz);                     \
            MMA_ACC(dR0, af[0][1], b2, b3);                                    \
            MMA_LD(dR1, af[1][0], b0, b1, fz, fz, fz, fz);                     \
            MMA_ACC(dR1, af[1][1], b2, b3);                                    \
            MMA_LD(dN0, af[4][0], b0, b1, bn4a, bn4a, bn4b, bn4b);             \
            MMA_ACC(dN0, af[4][1], b2, b3);                                    \
            MMA_LD(dN1, af[5][0], b0, b1, bn5a, bn5a, bn5b, bn5b);             \
            MMA_ACC(dN1, af[5][1], b2, b3);                                    \
            MMA_LD(dZ0, af[2][0], b0, b1, fz, fz, fz, fz);                     \
            MMA_ACC(dZ0, af[2][1], b2, b3);                                    \
            MMA_LD(dZ1, af[3][0], b0, b1, fz, fz, fz, fz);                     \
            MMA_ACC(dZ1, af[3][1], b2, b3);                                    \
            /* per-lane extraction: own unit's rows live in own c0/c2 */       \
            float rdot = p0 ? dR0[0] : p1 ? dR0[2] : p2 ? dR1[0] : dR1[2];     \
            float ndot = p0 ? dN0[0] : p1 ? dN0[2] : p2 ? dN1[0] : dN1[2];     \
            float zdot = p0 ? dZ0[0] : p1 ? dZ0[2] : p2 ? dZ1[0] : dZ1[2];     \
            float tr = tanhm(rdot + gx.x);                                     \
            float tz = tanhm(zdot + gx.y);                                     \
            float ns = ndot;                       /* 0.5*(Wn.h + bhn) */      \
            float nsc = gx.z + ns;                                             \
            float argn = fmaf(tr, ns, nsc);        /* xn + r*hn */             \
            float tn = tanhm(argn);                                            \
            float zz = fmaf(0.5f, tz, 0.5f);                                   \
            float cb = zz * hk;                                                \
            float ca = 1.0f - zz;                                              \
            hk = fmaf(ca, tn, cb);                 /* h_new (f32) */           \
            stv16((H16ROW) + u * 2, __half_as_ushort(__float2half_rn(hk)));    \
            sts32p((HROWF) + u * 4, hk);           /* exact copy for FC */     \
            hprev16 = (H16ROW);                                                \
        }

        for (int c = 0; c < NCH; c++) {
            __syncthreads();
            int nst = L - c * CH;
            nst = nst < 0 ? 0 : (nst > CH ? CH : nst);
            const int cb1 = c & 1;
            uint32_t h16row = h16base + (cb1 * CH * Hq) * 2;
            uint32_t hrowf = hbase + (cb1 * CH * HPAD) * 4;
            if (nst == CH) {
#pragma unroll 4
                for (int s = 0; s < CH; s++) {
                    GRU_STEP(cb1, s, h16row, hrowf)
                    h16row += Hq * 2;
                    hrowf += HPAD * 4;
                }
            } else {
#pragma unroll 1
                for (int s = 0; s < nst; s++) {
                    GRU_STEP(cb1, s, h16row, hrowf)
                    h16row += Hq * 2;
                    hrowf += HPAD * 4;
                }
            }
        }
        __syncthreads();
#undef GRU_STEP
    } else if (warp == 1) {
        // ================= FC output, one chunk behind =================
        for (int c = 0; c < NCH; c++) {
            __syncthreads();
            if (c > 0) {
                const int cp = c - 1;
                const int t = cp * CH + lane;
                float o0 = __ldg(fc_b + 0);
                float o1 = __ldg(fc_b + 1);
                if (t < L) {
                    const float* hr = &s_h[cp & 1][lane][0];
#pragma unroll
                    for (int j = 0; j < Hq; j++) {
                        float hv = hr[j];
                        o0 = fmaf(__ldg(fc_w + j), hv, o0);
                        o1 = fmaf(__ldg(fc_w + Hq + j), hv, o1);
                    }
                }
                float2 v = make_float2(o0, o1);
                *reinterpret_cast<float2*>(out + ((size_t)b * Tq + t) * Oq) = v;
            }
        }
        __syncthreads();
        {   // epilogue: last chunk
            const int cp = NCH - 1;
            const int t = cp * CH + lane;
            float o0 = __ldg(fc_b + 0);
            float o1 = __ldg(fc_b + 1);
            if (t < L) {
                const float* hr = &s_h[cp & 1][lane][0];
#pragma unroll
                for (int j = 0; j < Hq; j++) {
                    float hv = hr[j];
                    o0 = fmaf(__ldg(fc_w + j), hv, o0);
                    o1 = fmaf(__ldg(fc_w + Hq + j), hv, o1);
                }
            }
            float2 v = make_float2(o0, o1);
            *reinterpret_cast<float2*>(out + ((size_t)b * Tq + t) * Oq) = v;
        }
    } else {
        // ================= producers (warps 2,3), one chunk ahead =================
        float wiA[Iq], wiB[Iq], wiC[Iq];
#pragma unroll
        for (int i = 0; i < Iq; i++) {
            wiA[i] = 0.5f * w_ih[lane * Iq + i];          // pre-scaled for tanh-form
            wiB[i] = 0.5f * w_ih[(Hq + lane) * Iq + i];
            wiC[i] = w_ih[(2 * Hq + lane) * Iq + i];      // pn: unscaled
        }
        const float biA = 0.5f * (b_ih[lane] + b_hh[lane]);
        const float biB = 0.5f * (b_ih[Hq + lane] + b_hh[Hq + lane]);
        const float biC = b_ih[2 * Hq + lane];
        const int s0 = (warp == 3) ? (CH / 2) : 0;

        // prologue: chunk 0
        {
            const float* xp = x + ((size_t)b * Tq + s0) * Iq;
#pragma unroll 1
            for (int s = 0; s < CH / 2; s++) {
                float xv[Iq];
#pragma unroll
                for (int i = 0; i < Iq; i++) xv[i] = xp[i];
                float gr = biA, gz = biB, gn = biC;
#pragma unroll
                for (int i = 0; i < Iq; i++) {
                    gr = fmaf(wiA[i], xv[i], gr);
                    gz = fmaf(wiB[i], xv[i], gz);
                    gn = fmaf(wiC[i], xv[i], gn);
                }
                s_gx[0][s0 + s][lane] = make_float4(gr, gz, gn, 0.0f);
                xp += Iq;
            }
        }
        for (int c = 0; c < NCH; c++) {
            __syncthreads();
            const int cc = c + 1;
            if (cc < NCH) {
                const float* xp = x + ((size_t)b * Tq + cc * CH + s0) * Iq;
#pragma unroll 1
                for (int s = 0; s < CH / 2; s++) {
                    float xv[Iq];
#pragma unroll
                    for (int i = 0; i < Iq; i++) xv[i] = xp[i];
                    float gr = biA, gz = biB, gn = biC;
#pragma unroll
                    for (int i = 0; i < Iq; i++) {
                        gr = fmaf(wiA[i], xv[i], gr);
                        gz = fmaf(wiB[i], xv[i], gz);
                        gn = fmaf(wiC[i], xv[i], gn);
                    }
                    s_gx[cc & 1][s0 + s][lane] = make_float4(gr, gz, gn, 0.0f);
                    xp += Iq;
                }
            }
        }
        __syncthreads();
    }
}

extern "C" void kernel_launch(void* const* d_in, const int* in_sizes, int n_in,
                              void* d_out, int out_size) {
    const float* x       = (const float*)d_in[0];
    const int*   lengths = (const int*)d_in[1];
    const float* w_ih    = (const float*)d_in[2];
    const float* w_hh    = (const float*)d_in[3];
    const float* b_ih    = (const float*)d_in[4];
    const float* b_hh    = (const float*)d_in[5];
    const float* fc_w    = (const float*)d_in[6];
    const float* fc_b    = (const float*)d_in[7];
    float* out = (float*)d_out;

    gru_seq_kernel<<<Bq, 128>>>(x, lengths, w_ih, w_hh, b_ih, b_hh, fc_w, fc_b, out);
}